// round 9
// baseline (speedup 1.0000x reference)
#include <cuda_runtime.h>
#include <cstdint>

#define BATCH 8192
#define DIMN  4096
#define HIDN  256
#define NHEAD 16
#define SEQL  2048

// Static scratch (allocation-free). All K-axes stored in "fragment order":
// within each 16-float K group, position p holds logical k where
// p = ((k&3)<<2) | ((k>>2)&3)  (4x4 transpose, self-inverse).
__device__ float g_hidden[(size_t)BATCH * DIMN];   // tf32-rounded, K-permuted
__device__ float g_xr[(size_t)BATCH * DIMN];       // tf32-rounded, K-permuted
__device__ float g_bt1[(size_t)DIMN * DIMN];       // W_proj^T [(h*256+n)][k], rounded, K-permuted
__device__ float g_bt2[(size_t)DIMN * DIMN];       // W_out^T  [n][k], rounded, K-permuted

__device__ __forceinline__ float rna_tf32(float x) {
    float r;
    asm("cvt.rna.tf32.f32 %0, %1;" : "=f"(r) : "f"(x));
    return r;
}
__device__ __forceinline__ uint32_t smem_u32(const void* p) {
    uint32_t a;
    asm("{ .reg .u64 t; cvta.to.shared.u64 t, %1; cvt.u32.u64 %0, t; }"
        : "=r"(a) : "l"(p));
    return a;
}
__device__ __forceinline__ void lds128(uint32_t* v, uint32_t addr) {
    asm volatile("ld.shared.v4.b32 {%0,%1,%2,%3}, [%4];"
                 : "=r"(v[0]), "=r"(v[1]), "=r"(v[2]), "=r"(v[3]) : "r"(addr));
}

// ---------------------------------------------------------------------------
// Pre-pass kernels (validated in rounds 4-7)
// ---------------------------------------------------------------------------
__global__ void round_perm_kernel(const float4* __restrict__ src,
                                  float4* __restrict__ dst, int ngroups) {
    int gi = blockIdx.x * blockDim.x + threadIdx.x;
    if (gi >= ngroups) return;
    float4 i0 = src[gi * 4 + 0], i1 = src[gi * 4 + 1];
    float4 i2 = src[gi * 4 + 2], i3 = src[gi * 4 + 3];
    float4 o0 = { rna_tf32(i0.x), rna_tf32(i1.x), rna_tf32(i2.x), rna_tf32(i3.x) };
    float4 o1 = { rna_tf32(i0.y), rna_tf32(i1.y), rna_tf32(i2.y), rna_tf32(i3.y) };
    float4 o2 = { rna_tf32(i0.z), rna_tf32(i1.z), rna_tf32(i2.z), rna_tf32(i3.z) };
    float4 o3 = { rna_tf32(i0.w), rna_tf32(i1.w), rna_tf32(i2.w), rna_tf32(i3.w) };
    dst[gi * 4 + 0] = o0; dst[gi * 4 + 1] = o1;
    dst[gi * 4 + 2] = o2; dst[gi * 4 + 3] = o3;
}

// transpose + round + permute-K.  src: batch b of [R][C] row-major.
// dst[(b*C + c)][perm(r)] = rna(src[r][c]),  dst K-major with ld = R.
__global__ void transpose_round_kernel(const float* __restrict__ src,
                                       float* __restrict__ dst, int R, int C) {
    __shared__ float tile[32][33];
    const int b = blockIdx.z;
    const float* s = src + (size_t)b * R * C;
    const int c0 = blockIdx.x * 32, r0 = blockIdx.y * 32;
    const int tx = threadIdx.x, ty = threadIdx.y;
    #pragma unroll
    for (int j = 0; j < 4; j++)
        tile[ty + 8 * j][tx] = rna_tf32(s[(size_t)(r0 + ty + 8 * j) * C + c0 + tx]);
    __syncthreads();
    const int pc = r0 + ((tx & ~15) | ((tx & 3) << 2) | ((tx >> 2) & 3));
    #pragma unroll
    for (int j = 0; j < 4; j++)
        dst[(size_t)(b * C + c0 + ty + 8 * j) * R + pc] = tile[tx][ty + 8 * j];
}

// ---------------------------------------------------------------------------
// tf32 mma.sync GEMM. CTA 128x128x32, 256 thr, 8 warps (2M x 4N), warp tile
// 64x32 (round-3 skeleton), 3-stage cp.async, 96 KB -> 2 CTAs/SM.
// NEW: all fragment loads are LDS.128 over K-permuted data, from 12
// precomputed per-thread base addresses (g=1 group = XOR 64).
// MODE 1: C = rna( w*(acc+b_proj) + coef*cache + b_mix ), stored K-permuted
// MODE 2: C = acc + b_out   (plain layout)
// ---------------------------------------------------------------------------
template <int MODE>
__global__ __launch_bounds__(256, 2)
void gemm_tf32mma(const float* __restrict__ A, const float* __restrict__ B,
                  float* __restrict__ C,
                  const float* __restrict__ b_proj, const float* __restrict__ w_mix,
                  const float* __restrict__ b_mix, const float* __restrict__ decay_values,
                  const float* __restrict__ caches, const int* __restrict__ index_p,
                  const float* __restrict__ b_out)
{
    constexpr int BK = 32;
    constexpr int NT = DIMN / BK;                  // 128 k-slabs
    constexpr int A_BYTES = 128 * BK * 4;          // 16 KB
    constexpr int STAGE_BYTES = 2 * A_BYTES;       // 32 KB

    extern __shared__ float smem[];
    const uint32_t smem0 = smem_u32(smem);

    const int tid  = threadIdx.x;
    const int wid  = tid >> 5;
    const int lane = tid & 31;
    const int warpM = wid & 1;    // 0..1  (64 rows)
    const int warpN = wid >> 1;   // 0..3  (32 cols)
    const int grp = lane >> 2;    // 0..7
    const int tig = lane & 3;     // 0..3

    const int row0 = blockIdx.y * 128;
    const int n0   = blockIdx.x * 128;
    const float* aBase = A + (size_t)row0 * DIMN;
    const float* bBase = B + (size_t)n0 * DIMN;

    auto load = [&](uint32_t so, int kt) {
        const uint32_t sA = smem0 + so;
        const uint32_t sB = sA + A_BYTES;
        #pragma unroll
        for (int i = 0; i < 4; i++) {              // 1024 chunks each / 256 thr
            const int g = tid + i * 256;
            const int r = g >> 3, ch = g & 7;
            const uint32_t sw = (uint32_t)(r * 128 + ((ch ^ (r & 7)) << 4));
            asm volatile("cp.async.cg.shared.global [%0], [%1], 16;"
                         :: "r"(sA + sw), "l"(aBase + (size_t)r * DIMN + kt + ch * 4));
            asm volatile("cp.async.cg.shared.global [%0], [%1], 16;"
                         :: "r"(sB + sw), "l"(bBase + (size_t)r * DIMN + kt + ch * 4));
        }
        asm volatile("cp.async.commit_group;");
    };

    // Precomputed fragment base addresses (stage 0, K-group 0)
    uint32_t aAddr[4][2], bAddr[4];
    #pragma unroll
    for (int mi = 0; mi < 4; mi++)
        #pragma unroll
        for (int rh = 0; rh < 2; rh++) {
            const int r = warpM * 64 + mi * 16 + rh * 8 + grp;
            aAddr[mi][rh] = smem0 + (uint32_t)(r * 128 + ((tig ^ (r & 7)) << 4));
        }
    #pragma unroll
    for (int ni = 0; ni < 4; ni++) {
        const int nr = warpN * 32 + ni * 8 + grp;
        bAddr[ni] = smem0 + A_BYTES + (uint32_t)(nr * 128 + ((tig ^ (nr & 7)) << 4));
    }

    float acc[4][4][4];
    #pragma unroll
    for (int mi = 0; mi < 4; mi++)
        #pragma unroll
        for (int ni = 0; ni < 4; ni++)
            #pragma unroll
            for (int v = 0; v < 4; v++) acc[mi][ni][v] = 0.0f;

    load(0, 0);
    load(STAGE_BYTES, BK);

    uint32_t so_cur = 0, so_pre = 2 * STAGE_BYTES;
    for (int t = 0; t < NT; t++) {
        if (t < NT - 1) asm volatile("cp.async.wait_group 1;" ::: "memory");
        else            asm volatile("cp.async.wait_group 0;" ::: "memory");
        __syncthreads();

        if (t + 2 < NT) load(so_pre, (t + 2) * BK);

        #pragma unroll
        for (int g = 0; g < 2; g++) {
            const uint32_t gx = so_cur | (g << 6);   // stage offset + K-group XOR bit
            uint32_t bf[4][4];
            #pragma unroll
            for (int ni = 0; ni < 4; ni++)
                lds128(bf[ni], (bAddr[ni] + so_cur) ^ (g << 6));
            uint32_t af[2][2][4];
            lds128(af[0][0], (aAddr[0][0] + so_cur) ^ (g << 6));
            lds128(af[0][1], (aAddr[0][1] + so_cur) ^ (g << 6));
            #pragma unroll
            for (int mi = 0; mi < 4; mi++) {
                const int cur = mi & 1, nxt = cur ^ 1;
                if (mi < 3) {
                    lds128(af[nxt][0], (aAddr[mi + 1][0] + so_cur) ^ (g << 6));
                    lds128(af[nxt][1], (aAddr[mi + 1][1] + so_cur) ^ (g << 6));
                }
                #pragma unroll
                for (int s = 0; s < 2; s++)
                    #pragma unroll
                    for (int ni = 0; ni < 4; ni++)
                        asm volatile(
                            "mma.sync.aligned.m16n8k8.row.col.f32.tf32.tf32.f32 "
                            "{%0,%1,%2,%3}, {%4,%5,%6,%7}, {%8,%9}, {%0,%1,%2,%3};"
                            : "+f"(acc[mi][ni][0]), "+f"(acc[mi][ni][1]),
                              "+f"(acc[mi][ni][2]), "+f"(acc[mi][ni][3])
                            : "r"(af[cur][0][2 * s]), "r"(af[cur][1][2 * s]),
                              "r"(af[cur][0][2 * s + 1]), "r"(af[cur][1][2 * s + 1]),
                              "r"(bf[ni][2 * s]), "r"(bf[ni][2 * s + 1]));
            }
            (void)gx;
        }

        so_cur += STAGE_BYTES; if (so_cur == 3 * STAGE_BYTES) so_cur = 0;
        so_pre += STAGE_BYTES; if (so_pre == 3 * STAGE_BYTES) so_pre = 0;
    }

    // ------------------------------ epilogue ------------------------------
    if (MODE == 1) {
        const int h  = blockIdx.x >> 1;          // BN=128: two CTAs per head
        const int k0 = (blockIdx.x & 1) * 128;
        const int idx = *index_p;
        float dv = fminf(fmaxf(decay_values[h], 0.9f), 1.0f);
        const float decay = sqrtf(sqrtf(dv));
        const float w  = w_mix[(size_t)h * SEQL + idx];
        const float bb = b_mix[(size_t)h * SEQL + idx];
        const float coef = (h < NHEAD / 2) ? (w * decay) : decay;

        #pragma unroll
        for (int mi = 0; mi < 4; mi++) {
            #pragma unroll
            for (int rh = 0; rh < 2; rh++) {
                const int r = row0 + warpM * 64 + mi * 16 + rh * 8 + grp;
                const float* cacheRow = caches + ((size_t)h * BATCH + r) * HIDN;
                float* Crow = C + (size_t)r * DIMN + n0;
                #pragma unroll
                for (int ni = 0; ni < 4; ni++) {
                    #pragma unroll
                    for (int e = 0; e < 2; e++) {
                        const int cc = warpN * 32 + ni * 8 + 2 * tig + e;  // 0..127
                        const int k  = k0 + cc;                            // 0..255
                        float v = w * (acc[mi][ni][rh * 2 + e] + b_proj[h * HIDN + k])
                                + coef * cacheRow[k] + bb;
                        const int pcc = (cc & ~15) | ((cc & 3) << 2) | ((cc >> 2) & 3);
                        Crow[pcc] = rna_tf32(v);
                    }
                }
            }
        }
    } else {
        #pragma unroll
        for (int mi = 0; mi < 4; mi++) {
            #pragma unroll
            for (int rh = 0; rh < 2; rh++) {
                const int r = row0 + warpM * 64 + mi * 16 + rh * 8 + grp;
                float* Crow = C + (size_t)r * DIMN + n0;
                #pragma unroll
                for (int ni = 0; ni < 4; ni++) {
                    const int cc = warpN * 32 + ni * 8 + 2 * tig;
                    float2 v;
                    v.x = acc[mi][ni][rh * 2 + 0] + b_out[n0 + cc];
                    v.y = acc[mi][ni][rh * 2 + 1] + b_out[n0 + cc + 1];
                    *reinterpret_cast<float2*>(Crow + cc) = v;
                }
            }
        }
    }
}

// ---------------------------------------------------------------------------
extern "C" void kernel_launch(void* const* d_in, const int* in_sizes, int n_in,
                              void* d_out, int out_size)
{
    const float* x       = (const float*)d_in[0];
    const int*   index_p = (const int*)  d_in[1];
    const float* W_proj  = (const float*)d_in[2];
    const float* b_proj  = (const float*)d_in[3];
    const float* W_out   = (const float*)d_in[4];
    const float* b_out   = (const float*)d_in[5];
    const float* w_mix   = (const float*)d_in[6];
    const float* b_mix   = (const float*)d_in[7];
    const float* decay   = (const float*)d_in[8];
    const float* caches  = (const float*)d_in[9];
    float* out = (float*)d_out;

    float *hidden, *xr, *bt1, *bt2;
    cudaGetSymbolAddress((void**)&hidden, g_hidden);
    cudaGetSymbolAddress((void**)&xr,     g_xr);
    cudaGetSymbolAddress((void**)&bt1,    g_bt1);
    cudaGetSymbolAddress((void**)&bt2,    g_bt2);

    const int SMEM_DYN = 3 * 2 * 128 * 32 * 4;   // 96 KB
    cudaFuncSetAttribute(gemm_tf32mma<1>, cudaFuncAttributeMaxDynamicSharedMemorySize, SMEM_DYN);
    cudaFuncSetAttribute(gemm_tf32mma<2>, cudaFuncAttributeMaxDynamicSharedMemorySize, SMEM_DYN);

    {
        const int ng = (BATCH * DIMN) / 16;
        round_perm_kernel<<<(ng + 255) / 256, 256>>>((const float4*)x, (float4*)xr, ng);
    }
    transpose_round_kernel<<<dim3(HIDN / 32, DIMN / 32, NHEAD), dim3(32, 8)>>>(
        W_proj, bt1, DIMN, HIDN);
    transpose_round_kernel<<<dim3(DIMN / 32, DIMN / 32, 1), dim3(32, 8)>>>(
        W_out, bt2, DIMN, DIMN);

    dim3 grid(DIMN / 128, BATCH / 128);   // 32 x 64
    gemm_tf32mma<1><<<grid, 256, SMEM_DYN>>>(xr, bt1, hidden,
                                             b_proj, w_mix, b_mix, decay, caches,
                                             index_p, b_out);
    gemm_tf32mma<2><<<grid, 256, SMEM_DYN>>>(hidden, bt2, out,
                                             b_proj, w_mix, b_mix, decay, caches,
                                             index_p, b_out);
}

// round 10
// speedup vs baseline: 1.1048x; 1.1048x over previous
#include <cuda_runtime.h>
#include <cstdint>

#define BATCH 8192
#define DIMN  4096
#define HIDN  256
#define NHEAD 16
#define SEQL  2048

// Static scratch. K-axes stored in "fragment order": within each 16-float
// K group, position p holds logical k where p = ((k&3)<<2)|((k>>2)&3).
__device__ float g_hidden[(size_t)BATCH * DIMN];   // tf32-rounded, K-permuted
__device__ float g_xr[(size_t)BATCH * DIMN];       // tf32-rounded, K-permuted
__device__ float g_bt1[(size_t)DIMN * DIMN];       // W_proj^T [(h*256+n)][k], rounded, perm
__device__ float g_bt2[(size_t)DIMN * DIMN];       // W_out^T  [n][k], rounded, perm

__device__ __forceinline__ float rna_tf32(float x) {
    float r;
    asm("cvt.rna.tf32.f32 %0, %1;" : "=f"(r) : "f"(x));
    return r;
}
__device__ __forceinline__ uint32_t smem_u32(const void* p) {
    uint32_t a;
    asm("{ .reg .u64 t; cvta.to.shared.u64 t, %1; cvt.u32.u64 %0, t; }"
        : "=r"(a) : "l"(p));
    return a;
}
__device__ __forceinline__ void lds128(uint32_t* v, uint32_t addr) {
    asm volatile("ld.shared.v4.b32 {%0,%1,%2,%3}, [%4];"
                 : "=r"(v[0]), "=r"(v[1]), "=r"(v[2]), "=r"(v[3]) : "r"(addr));
}

// ---------------------------------------------------------------------------
// Pre-pass kernels (validated rounds 4-9)
// ---------------------------------------------------------------------------
__global__ void round_perm_kernel(const float4* __restrict__ src,
                                  float4* __restrict__ dst, int ngroups) {
    int gi = blockIdx.x * blockDim.x + threadIdx.x;
    if (gi >= ngroups) return;
    float4 i0 = src[gi * 4 + 0], i1 = src[gi * 4 + 1];
    float4 i2 = src[gi * 4 + 2], i3 = src[gi * 4 + 3];
    float4 o0 = { rna_tf32(i0.x), rna_tf32(i1.x), rna_tf32(i2.x), rna_tf32(i3.x) };
    float4 o1 = { rna_tf32(i0.y), rna_tf32(i1.y), rna_tf32(i2.y), rna_tf32(i3.y) };
    float4 o2 = { rna_tf32(i0.z), rna_tf32(i1.z), rna_tf32(i2.z), rna_tf32(i3.z) };
    float4 o3 = { rna_tf32(i0.w), rna_tf32(i1.w), rna_tf32(i2.w), rna_tf32(i3.w) };
    dst[gi * 4 + 0] = o0; dst[gi * 4 + 1] = o1;
    dst[gi * 4 + 2] = o2; dst[gi * 4 + 3] = o3;
}

// transpose + round + permute-K.  src: batch b of [R][C] row-major.
// dst[(b*C + c)][perm(r)] = rna(src[r][c]),  dst K-major with ld = R.
__global__ void transpose_round_kernel(const float* __restrict__ src,
                                       float* __restrict__ dst, int R, int C) {
    __shared__ float tile[32][33];
    const int b = blockIdx.z;
    const float* s = src + (size_t)b * R * C;
    const int c0 = blockIdx.x * 32, r0 = blockIdx.y * 32;
    const int tx = threadIdx.x, ty = threadIdx.y;
    #pragma unroll
    for (int j = 0; j < 4; j++)
        tile[ty + 8 * j][tx] = rna_tf32(s[(size_t)(r0 + ty + 8 * j) * C + c0 + tx]);
    __syncthreads();
    const int pc = r0 + ((tx & ~15) | ((tx & 3) << 2) | ((tx >> 2) & 3));
    #pragma unroll
    for (int j = 0; j < 4; j++)
        dst[(size_t)(b * C + c0 + ty + 8 * j) * R + pc] = tile[tx][ty + 8 * j];
}

// ---------------------------------------------------------------------------
// tf32 mma.sync GEMM. CTA 128x128x32, 256 thr, 8 warps (2M x 4N), warp tile
// 64x32, 3-stage cp.async, 96 KB -> 2 CTAs/SM.
// SMEM stage layout (no swizzle): chunk(g,row,tig) at g*8192 + row*64 + tig*16,
// chunk = 4 floats, logical k in {16g + tig + 0,4,8,12} (K-permuted gmem).
// STS: consecutive threads -> consecutive 16B (conflict-free).
// Fragment LDS.128: quarter-warp = 2 rows x 64B contiguous (conflict-free),
// all offsets are compile-time immediates off one per-slab base register.
// MODE 1: C = rna( w*(acc+b_proj) + coef*cache + b_mix ), stored K-permuted
// MODE 2: C = acc + b_out   (plain layout)
// ---------------------------------------------------------------------------
template <int MODE>
__global__ __launch_bounds__(256, 2)
void gemm_tf32mma(const float* __restrict__ A, const float* __restrict__ B,
                  float* __restrict__ C,
                  const float* __restrict__ b_proj, const float* __restrict__ w_mix,
                  const float* __restrict__ b_mix, const float* __restrict__ decay_values,
                  const float* __restrict__ caches, const int* __restrict__ index_p,
                  const float* __restrict__ b_out)
{
    constexpr int BK = 32;
    constexpr int NT = DIMN / BK;                  // 128 k-slabs
    constexpr int A_BYTES = 128 * BK * 4;          // 16 KB
    constexpr int STAGE_BYTES = 2 * A_BYTES;       // 32 KB

    extern __shared__ float smem[];
    const uint32_t smem0 = smem_u32(smem);

    const int tid  = threadIdx.x;
    const int wid  = tid >> 5;
    const int lane = tid & 31;
    const int warpM = wid & 1;    // 0..1  (64 rows)
    const int warpN = wid >> 1;   // 0..3  (32 cols)
    const int grp = lane >> 2;    // 0..7
    const int tig = lane & 3;     // 0..3

    const int row0 = blockIdx.y * 128;
    const int n0   = blockIdx.x * 128;
    const float* aBase = A + (size_t)row0 * DIMN;
    const float* bBase = B + (size_t)n0 * DIMN;

    // loader: 1024 chunks per operand, 4 per thread, linear smem addresses
    auto load = [&](uint32_t so, int kt) {
        const uint32_t sA = smem0 + so;
        const uint32_t sB = sA + A_BYTES;
        #pragma unroll
        for (int i = 0; i < 4; i++) {
            const int c  = tid + i * 256;          // 0..1023
            const int g  = c >> 9;                 // 0..1
            const int r  = (c >> 2) & 127;         // row
            const int tg = c & 3;                  // chunk-in-group
            const uint32_t soff = (uint32_t)(g * 8192 + r * 64 + tg * 16);
            const float* sa = aBase + (size_t)r * DIMN + kt + g * 16 + tg * 4;
            const float* sb = bBase + (size_t)r * DIMN + kt + g * 16 + tg * 4;
            asm volatile("cp.async.cg.shared.global [%0], [%1], 16;"
                         :: "r"(sA + soff), "l"(sa));
            asm volatile("cp.async.cg.shared.global [%0], [%1], 16;"
                         :: "r"(sB + soff), "l"(sb));
        }
        asm volatile("cp.async.commit_group;");
    };

    // fragment base offsets (stage-relative, all further offsets immediate)
    const uint32_t aFragBase = smem0 + (uint32_t)((warpM * 64 + grp) * 64 + tig * 16);
    const uint32_t bFragBase = smem0 + A_BYTES
                             + (uint32_t)((warpN * 32 + grp) * 64 + tig * 16);

    float acc[4][4][4];
    #pragma unroll
    for (int mi = 0; mi < 4; mi++)
        #pragma unroll
        for (int ni = 0; ni < 4; ni++)
            #pragma unroll
            for (int v = 0; v < 4; v++) acc[mi][ni][v] = 0.0f;

    load(0, 0);
    load(STAGE_BYTES, BK);

    uint32_t so_cur = 0, so_pre = 2 * STAGE_BYTES;
    for (int t = 0; t < NT; t++) {
        if (t < NT - 1) asm volatile("cp.async.wait_group 1;" ::: "memory");
        else            asm volatile("cp.async.wait_group 0;" ::: "memory");
        __syncthreads();

        if (t + 2 < NT) load(so_pre, (t + 2) * BK);

        const uint32_t aFB = aFragBase + so_cur;
        const uint32_t bFB = bFragBase + so_cur;

        #pragma unroll
        for (int g = 0; g < 2; g++) {
            // B fragments: 4 LDS.128 (covers ki = 2g, 2g+1)
            uint32_t bf[4][4];
            #pragma unroll
            for (int ni = 0; ni < 4; ni++)
                lds128(bf[ni], bFB + g * 8192 + ni * 512);
            // A fragments: 8 LDS.128
            uint32_t af[4][2][4];
            #pragma unroll
            for (int mi = 0; mi < 4; mi++)
                #pragma unroll
                for (int rh = 0; rh < 2; rh++)
                    lds128(af[mi][rh], aFB + g * 8192 + mi * 1024 + rh * 512);

            #pragma unroll
            for (int s = 0; s < 2; s++)
                #pragma unroll
                for (int mi = 0; mi < 4; mi++)
                    #pragma unroll
                    for (int ni = 0; ni < 4; ni++)
                        asm volatile(
                            "mma.sync.aligned.m16n8k8.row.col.f32.tf32.tf32.f32 "
                            "{%0,%1,%2,%3}, {%4,%5,%6,%7}, {%8,%9}, {%0,%1,%2,%3};"
                            : "+f"(acc[mi][ni][0]), "+f"(acc[mi][ni][1]),
                              "+f"(acc[mi][ni][2]), "+f"(acc[mi][ni][3])
                            : "r"(af[mi][0][2 * s]), "r"(af[mi][1][2 * s]),
                              "r"(af[mi][0][2 * s + 1]), "r"(af[mi][1][2 * s + 1]),
                              "r"(bf[ni][2 * s]), "r"(bf[ni][2 * s + 1]));
        }

        so_cur += STAGE_BYTES; if (so_cur == 3 * STAGE_BYTES) so_cur = 0;
        so_pre += STAGE_BYTES; if (so_pre == 3 * STAGE_BYTES) so_pre = 0;
    }

    // ------------------------------ epilogue ------------------------------
    if (MODE == 1) {
        const int h  = blockIdx.x >> 1;          // BN=128: two CTAs per head
        const int k0 = (blockIdx.x & 1) * 128;
        const int idx = *index_p;
        float dv = fminf(fmaxf(decay_values[h], 0.9f), 1.0f);
        const float decay = sqrtf(sqrtf(dv));
        const float w  = w_mix[(size_t)h * SEQL + idx];
        const float bb = b_mix[(size_t)h * SEQL + idx];
        const float coef = (h < NHEAD / 2) ? (w * decay) : decay;

        #pragma unroll
        for (int mi = 0; mi < 4; mi++) {
            #pragma unroll
            for (int rh = 0; rh < 2; rh++) {
                const int r = row0 + warpM * 64 + mi * 16 + rh * 8 + grp;
                const float* cacheRow = caches + ((size_t)h * BATCH + r) * HIDN;
                float* Crow = C + (size_t)r * DIMN + n0;
                #pragma unroll
                for (int ni = 0; ni < 4; ni++) {
                    #pragma unroll
                    for (int e = 0; e < 2; e++) {
                        const int cc = warpN * 32 + ni * 8 + 2 * tig + e;  // 0..127
                        const int k  = k0 + cc;                            // 0..255
                        float v = w * (acc[mi][ni][rh * 2 + e] + b_proj[h * HIDN + k])
                                + coef * cacheRow[k] + bb;
                        const int pcc = (cc & ~15) | ((cc & 3) << 2) | ((cc >> 2) & 3);
                        Crow[pcc] = rna_tf32(v);
                    }
                }
            }
        }
    } else {
        #pragma unroll
        for (int mi = 0; mi < 4; mi++) {
            #pragma unroll
            for (int rh = 0; rh < 2; rh++) {
                const int r = row0 + warpM * 64 + mi * 16 + rh * 8 + grp;
                float* Crow = C + (size_t)r * DIMN + n0;
                #pragma unroll
                for (int ni = 0; ni < 4; ni++) {
                    const int cc = warpN * 32 + ni * 8 + 2 * tig;
                    float2 v;
                    v.x = acc[mi][ni][rh * 2 + 0] + b_out[n0 + cc];
                    v.y = acc[mi][ni][rh * 2 + 1] + b_out[n0 + cc + 1];
                    *reinterpret_cast<float2*>(Crow + cc) = v;
                }
            }
        }
    }
}

// ---------------------------------------------------------------------------
extern "C" void kernel_launch(void* const* d_in, const int* in_sizes, int n_in,
                              void* d_out, int out_size)
{
    const float* x       = (const float*)d_in[0];
    const int*   index_p = (const int*)  d_in[1];
    const float* W_proj  = (const float*)d_in[2];
    const float* b_proj  = (const float*)d_in[3];
    const float* W_out   = (const float*)d_in[4];
    const float* b_out   = (const float*)d_in[5];
    const float* w_mix   = (const float*)d_in[6];
    const float* b_mix   = (const float*)d_in[7];
    const float* decay   = (const float*)d_in[8];
    const float* caches  = (const float*)d_in[9];
    float* out = (float*)d_out;

    float *hidden, *xr, *bt1, *bt2;
    cudaGetSymbolAddress((void**)&hidden, g_hidden);
    cudaGetSymbolAddress((void**)&xr,     g_xr);
    cudaGetSymbolAddress((void**)&bt1,    g_bt1);
    cudaGetSymbolAddress((void**)&bt2,    g_bt2);

    const int SMEM_DYN = 3 * 2 * 128 * 32 * 4;   // 96 KB
    cudaFuncSetAttribute(gemm_tf32mma<1>, cudaFuncAttributeMaxDynamicSharedMemorySize, SMEM_DYN);
    cudaFuncSetAttribute(gemm_tf32mma<2>, cudaFuncAttributeMaxDynamicSharedMemorySize, SMEM_DYN);

    {
        const int ng = (BATCH * DIMN) / 16;
        round_perm_kernel<<<(ng + 255) / 256, 256>>>((const float4*)x, (float4*)xr, ng);
    }
    transpose_round_kernel<<<dim3(HIDN / 32, DIMN / 32, NHEAD), dim3(32, 8)>>>(
        W_proj, bt1, DIMN, HIDN);
    transpose_round_kernel<<<dim3(DIMN / 32, DIMN / 32, 1), dim3(32, 8)>>>(
        W_out, bt2, DIMN, DIMN);

    dim3 grid(DIMN / 128, BATCH / 128);   // 32 x 64
    gemm_tf32mma<1><<<grid, 256, SMEM_DYN>>>(xr, bt1, hidden,
                                             b_proj, w_mix, b_mix, decay, caches,
                                             index_p, b_out);
    gemm_tf32mma<2><<<grid, 256, SMEM_DYN>>>(hidden, bt2, out,
                                             b_proj, w_mix, b_mix, decay, caches,
                                             index_p, b_out);
}

// round 14
// speedup vs baseline: 1.2810x; 1.1594x over previous
#include <cuda_runtime.h>
#include <cstdint>

#define BATCH 8192
#define DIMN  4096
#define HIDN  256
#define NHEAD 16
#define SEQL  2048

// Static scratch (allocation-free)
__device__ float g_hidden[(size_t)BATCH * DIMN];   // tf32-rounded hidden
__device__ float g_xr[(size_t)BATCH * DIMN];       // tf32-rounded x
__device__ float g_bt1[(size_t)DIMN * DIMN];       // W_proj^T per head: [(h*256+n)][k]
__device__ float g_bt2[(size_t)DIMN * DIMN];       // W_out^T: [n][k]

__device__ __forceinline__ float rna_tf32(float x) {
    float r;
    asm("cvt.rna.tf32.f32 %0, %1;" : "=f"(r) : "f"(x));
    return r;
}
__device__ __forceinline__ uint32_t smem_u32(const void* p) {
    uint32_t a;
    asm("{ .reg .u64 t; cvta.to.shared.u64 t, %1; cvt.u32.u64 %0, t; }"
        : "=r"(a) : "l"(p));
    return a;
}

// ---------------------------------------------------------------------------
// Pre-pass kernels (round-3 originals: plain layout, no K-permutation)
// ---------------------------------------------------------------------------
__global__ void round_tf32_kernel(const float4* __restrict__ src,
                                  float4* __restrict__ dst, int n4) {
    int i = blockIdx.x * blockDim.x + threadIdx.x;
    if (i < n4) {
        float4 v = src[i];
        v.x = rna_tf32(v.x); v.y = rna_tf32(v.y);
        v.z = rna_tf32(v.z); v.w = rna_tf32(v.w);
        dst[i] = v;
    }
}

// src: batch b of [R][C] row-major.  dst[(b*C + c)*R + r] = rna(src[r][c])
__global__ void transpose_round_kernel(const float* __restrict__ src,
                                       float* __restrict__ dst, int R, int C) {
    __shared__ float tile[32][33];
    const int b = blockIdx.z;
    const float* s = src + (size_t)b * R * C;
    const int c0 = blockIdx.x * 32, r0 = blockIdx.y * 32;
    const int tx = threadIdx.x, ty = threadIdx.y;
    #pragma unroll
    for (int j = 0; j < 4; j++)
        tile[ty + 8 * j][tx] = rna_tf32(s[(size_t)(r0 + ty + 8 * j) * C + c0 + tx]);
    __syncthreads();
    #pragma unroll
    for (int j = 0; j < 4; j++)
        dst[(size_t)(b * C + c0 + ty + 8 * j) * R + r0 + tx] = tile[tx][ty + 8 * j];
}

// ---------------------------------------------------------------------------
// tf32 mma.sync GEMM — round-3 champion structure, untouched mainloop.
// CTA 128x128x32, 3-stage cp.async, 8 warps (2M x 4N), warp tile 64x32,
// mma m16n8k8. A [M,K] row-major, B [N,K] n-major.
// MODE 1: C = rna( w*(acc+b_proj) + coef*cache + b_mix )
// MODE 2: C = acc + b_out
// ---------------------------------------------------------------------------
template <int MODE>
__global__ __launch_bounds__(256)
void gemm_tf32mma(const float* __restrict__ A, const float* __restrict__ B,
                  float* __restrict__ C,
                  const float* __restrict__ b_proj, const float* __restrict__ w_mix,
                  const float* __restrict__ b_mix, const float* __restrict__ decay_values,
                  const float* __restrict__ caches, const int* __restrict__ index_p,
                  const float* __restrict__ b_out)
{
    constexpr int BK = 32;
    constexpr int NS = 3;
    constexpr int NT = DIMN / BK;              // 128 k-slabs
    constexpr int STAGE_FLOATS = 2 * 128 * BK; // A(16KB) + B(16KB)

    extern __shared__ float smem[];

    const int tid  = threadIdx.x;
    const int wid  = tid >> 5;
    const int lane = tid & 31;
    const int warpM = wid & 1;    // 0..1
    const int warpN = wid >> 1;   // 0..3
    const int grp = lane >> 2;    // 0..7
    const int tig = lane & 3;     // 0..3

    const int row0 = blockIdx.y * 128;
    const int n0   = blockIdx.x * 128;
    const float* aBase = A + (size_t)row0 * DIMN;
    const float* bBase = B + (size_t)n0 * DIMN;

    // ---- async tile loader: 128 rows x 8 chunks(16B) each for A and B ----
    auto load = [&](int s, int kt) {
        const uint32_t sA = smem_u32(smem + s * STAGE_FLOATS);
        const uint32_t sB = sA + 16384;
        #pragma unroll
        for (int i = 0; i < 4; i++) {
            const int g = tid + i * 256;       // 0..1023
            const int r = g >> 3, ch = g & 7;
            const uint32_t swoff = (uint32_t)(r * 128 + ((ch ^ (r & 7)) << 4));
            const float* srcA = aBase + (size_t)r * DIMN + kt + ch * 4;
            const float* srcB = bBase + (size_t)r * DIMN + kt + ch * 4;
            asm volatile("cp.async.cg.shared.global [%0], [%1], 16;"
                         :: "r"(sA + swoff), "l"(srcA));
            asm volatile("cp.async.cg.shared.global [%0], [%1], 16;"
                         :: "r"(sB + swoff), "l"(srcB));
        }
        asm volatile("cp.async.commit_group;");
    };

    float acc[4][4][4];
    #pragma unroll
    for (int mi = 0; mi < 4; mi++)
        #pragma unroll
        for (int ni = 0; ni < 4; ni++)
            #pragma unroll
            for (int v = 0; v < 4; v++) acc[mi][ni][v] = 0.0f;

    load(0, 0);
    load(1, BK);

    for (int t = 0; t < NT; t++) {
        if (t < NT - 1) asm volatile("cp.async.wait_group 1;" ::: "memory");
        else            asm volatile("cp.async.wait_group 0;" ::: "memory");
        __syncthreads();

        if (t + 2 < NT) load((t + 2) % NS, (t + 2) * BK);

        const char* stA = (const char*)(smem + (t % NS) * STAGE_FLOATS);
        const char* stB = stA + 16384;

        #pragma unroll
        for (int ki = 0; ki < 4; ki++) {
            // A fragments
            uint32_t a[4][4];
            #pragma unroll
            for (int mi = 0; mi < 4; mi++) {
                const int r0 = warpM * 64 + mi * 16 + grp;
                const int r1 = r0 + 8;
                const int c4 = tig * 4;
                const int ch0 = ki * 2, ch1 = ki * 2 + 1;
                a[mi][0] = *(const uint32_t*)(stA + r0 * 128 + ((ch0 ^ (r0 & 7)) << 4) + c4);
                a[mi][1] = *(const uint32_t*)(stA + r1 * 128 + ((ch0 ^ (r1 & 7)) << 4) + c4);
                a[mi][2] = *(const uint32_t*)(stA + r0 * 128 + ((ch1 ^ (r0 & 7)) << 4) + c4);
                a[mi][3] = *(const uint32_t*)(stA + r1 * 128 + ((ch1 ^ (r1 & 7)) << 4) + c4);
            }
            // B fragments
            uint32_t b[4][2];
            #pragma unroll
            for (int ni = 0; ni < 4; ni++) {
                const int nr = warpN * 32 + ni * 8 + grp;
                const int c4 = tig * 4;
                const int ch0 = ki * 2, ch1 = ki * 2 + 1;
                b[ni][0] = *(const uint32_t*)(stB + nr * 128 + ((ch0 ^ (nr & 7)) << 4) + c4);
                b[ni][1] = *(const uint32_t*)(stB + nr * 128 + ((ch1 ^ (nr & 7)) << 4) + c4);
            }
            #pragma unroll
            for (int mi = 0; mi < 4; mi++)
                #pragma unroll
                for (int ni = 0; ni < 4; ni++)
                    asm volatile(
                        "mma.sync.aligned.m16n8k8.row.col.f32.tf32.tf32.f32 "
                        "{%0,%1,%2,%3}, {%4,%5,%6,%7}, {%8,%9}, {%0,%1,%2,%3};"
                        : "+f"(acc[mi][ni][0]), "+f"(acc[mi][ni][1]),
                          "+f"(acc[mi][ni][2]), "+f"(acc[mi][ni][3])
                        : "r"(a[mi][0]), "r"(a[mi][1]), "r"(a[mi][2]), "r"(a[mi][3]),
                          "r"(b[ni][0]), "r"(b[ni][1]));
        }
    }

    // ------------------------------ epilogue (float2 stores) --------------
    if (MODE == 1) {
        const int h  = blockIdx.x >> 1;
        const int k0 = (blockIdx.x & 1) * 128;
        const int idx = *index_p;
        float dv = fminf(fmaxf(decay_values[h], 0.9f), 1.0f);
        const float decay = sqrtf(sqrtf(dv));
        const float w  = w_mix[(size_t)h * SEQL + idx];
        const float bb = b_mix[(size_t)h * SEQL + idx];
        const float coef = (h < NHEAD / 2) ? (w * decay) : decay;

        #pragma unroll
        for (int mi = 0; mi < 4; mi++) {
            #pragma unroll
            for (int half = 0; half < 2; half++) {
                const int r = row0 + warpM * 64 + mi * 16 + grp + half * 8;
                const float* cacheRow = caches + ((size_t)h * BATCH + r) * HIDN;
                float* Crow = C + (size_t)r * DIMN + n0;
                #pragma unroll
                for (int ni = 0; ni < 4; ni++) {
                    const int cc = warpN * 32 + ni * 8 + 2 * tig;   // even
                    const int k  = k0 + cc;
                    float2 v;
                    v.x = rna_tf32(w * (acc[mi][ni][half * 2 + 0] + b_proj[h * HIDN + k])
                                   + coef * cacheRow[k] + bb);
                    v.y = rna_tf32(w * (acc[mi][ni][half * 2 + 1] + b_proj[h * HIDN + k + 1])
                                   + coef * cacheRow[k + 1] + bb);
                    *reinterpret_cast<float2*>(Crow + cc) = v;
                }
            }
        }
    } else {
        #pragma unroll
        for (int mi = 0; mi < 4; mi++) {
            #pragma unroll
            for (int half = 0; half < 2; half++) {
                const int r = row0 + warpM * 64 + mi * 16 + grp + half * 8;
                float* Crow = C + (size_t)r * DIMN + n0;
                #pragma unroll
                for (int ni = 0; ni < 4; ni++) {
                    const int cc = warpN * 32 + ni * 8 + 2 * tig;
                    float2 v;
                    v.x = acc[mi][ni][half * 2 + 0] + b_out[n0 + cc];
                    v.y = acc[mi][ni][half * 2 + 1] + b_out[n0 + cc + 1];
                    *reinterpret_cast<float2*>(Crow + cc) = v;
                }
            }
        }
    }
}

// ---------------------------------------------------------------------------
extern "C" void kernel_launch(void* const* d_in, const int* in_sizes, int n_in,
                              void* d_out, int out_size)
{
    const float* x       = (const float*)d_in[0];
    const int*   index_p = (const int*)  d_in[1];
    const float* W_proj  = (const float*)d_in[2];
    const float* b_proj  = (const float*)d_in[3];
    const float* W_out   = (const float*)d_in[4];
    const float* b_out   = (const float*)d_in[5];
    const float* w_mix   = (const float*)d_in[6];
    const float* b_mix   = (const float*)d_in[7];
    const float* decay   = (const float*)d_in[8];
    const float* caches  = (const float*)d_in[9];
    float* out = (float*)d_out;

    float *hidden, *xr, *bt1, *bt2;
    cudaGetSymbolAddress((void**)&hidden, g_hidden);
    cudaGetSymbolAddress((void**)&xr,     g_xr);
    cudaGetSymbolAddress((void**)&bt1,    g_bt1);
    cudaGetSymbolAddress((void**)&bt2,    g_bt2);

    const int SMEM_DYN = 3 * 2 * 128 * 32 * 4;  // 96 KB
    cudaFuncSetAttribute(gemm_tf32mma<1>, cudaFuncAttributeMaxDynamicSharedMemorySize, SMEM_DYN);
    cudaFuncSetAttribute(gemm_tf32mma<2>, cudaFuncAttributeMaxDynamicSharedMemorySize, SMEM_DYN);

    {
        const int n4 = (BATCH * DIMN) / 4;
        round_tf32_kernel<<<(n4 + 255) / 256, 256>>>((const float4*)x, (float4*)xr, n4);
    }
    transpose_round_kernel<<<dim3(HIDN / 32, DIMN / 32, NHEAD), dim3(32, 8)>>>(
        W_proj, bt1, DIMN, HIDN);
    transpose_round_kernel<<<dim3(DIMN / 32, DIMN / 32, 1), dim3(32, 8)>>>(
        W_out, bt2, DIMN, DIMN);

    dim3 grid(DIMN / 128, BATCH / 128);   // 32 x 64
    gemm_tf32mma<1><<<grid, 256, SMEM_DYN>>>(xr, bt1, hidden,
                                             b_proj, w_mix, b_mix, decay, caches,
                                             index_p, b_out);
    gemm_tf32mma<2><<<grid, 256, SMEM_DYN>>>(hidden, bt2, out,
                                             b_proj, w_mix, b_mix, decay, caches,
                                             index_p, b_out);
}

// round 15
// speedup vs baseline: 1.4104x; 1.1010x over previous
#include <cuda_runtime.h>
#include <cstdint>

#define BATCH 8192
#define DIMN  4096
#define HIDN  256
#define NHEAD 16
#define SEQL  2048

// Static scratch (allocation-free)
__device__ float g_hidden[(size_t)BATCH * DIMN];   // tf32-rounded hidden
__device__ float g_xr[(size_t)BATCH * DIMN];       // tf32-rounded x
__device__ float g_bt1[(size_t)DIMN * DIMN];       // W_proj^T per head: [(h*256+n)][k]
__device__ float g_bt2[(size_t)DIMN * DIMN];       // W_out^T: [n][k]

__device__ __forceinline__ float rna_tf32(float x) {
    float r;
    asm("cvt.rna.tf32.f32 %0, %1;" : "=f"(r) : "f"(x));
    return r;
}
__device__ __forceinline__ uint32_t smem_u32(const void* p) {
    uint32_t a;
    asm("{ .reg .u64 t; cvta.to.shared.u64 t, %1; cvt.u32.u64 %0, t; }"
        : "=r"(a) : "l"(p));
    return a;
}
// 4x 8-row-of-16B matrices; for fp32 data each matrix is 8x4, thread i gets
// element (row i/4, col i%4) of matrix j in reg j — identical to LDS.32 layout.
__device__ __forceinline__ void ldsm4(uint32_t* v, uint32_t addr) {
    asm volatile("ldmatrix.sync.aligned.m8n8.x4.shared.b16 {%0,%1,%2,%3}, [%4];"
                 : "=r"(v[0]), "=r"(v[1]), "=r"(v[2]), "=r"(v[3]) : "r"(addr));
}

// ---------------------------------------------------------------------------
// Pre-pass kernels (round-3 originals: plain layout, no K-permutation)
// ---------------------------------------------------------------------------
__global__ void round_tf32_kernel(const float4* __restrict__ src,
                                  float4* __restrict__ dst, int n4) {
    int i = blockIdx.x * blockDim.x + threadIdx.x;
    if (i < n4) {
        float4 v = src[i];
        v.x = rna_tf32(v.x); v.y = rna_tf32(v.y);
        v.z = rna_tf32(v.z); v.w = rna_tf32(v.w);
        dst[i] = v;
    }
}

// src: batch b of [R][C] row-major.  dst[(b*C + c)*R + r] = rna(src[r][c])
__global__ void transpose_round_kernel(const float* __restrict__ src,
                                       float* __restrict__ dst, int R, int C) {
    __shared__ float tile[32][33];
    const int b = blockIdx.z;
    const float* s = src + (size_t)b * R * C;
    const int c0 = blockIdx.x * 32, r0 = blockIdx.y * 32;
    const int tx = threadIdx.x, ty = threadIdx.y;
    #pragma unroll
    for (int j = 0; j < 4; j++)
        tile[ty + 8 * j][tx] = rna_tf32(s[(size_t)(r0 + ty + 8 * j) * C + c0 + tx]);
    __syncthreads();
    #pragma unroll
    for (int j = 0; j < 4; j++)
        dst[(size_t)(b * C + c0 + ty + 8 * j) * R + r0 + tx] = tile[tx][ty + 8 * j];
}

// ---------------------------------------------------------------------------
// tf32 mma.sync GEMM — round-3 champion structure; fragment loads via
// ldmatrix.x4 (same layout/swizzle/contents, 4x fewer load instructions).
// CTA 128x128x32, 3-stage cp.async, 8 warps (2M x 4N), warp tile 64x32.
// MODE 1: C = rna( w*(acc+b_proj) + coef*cache + b_mix )
// MODE 2: C = acc + b_out
// ---------------------------------------------------------------------------
template <int MODE>
__global__ __launch_bounds__(256)
void gemm_tf32mma(const float* __restrict__ A, const float* __restrict__ B,
                  float* __restrict__ C,
                  const float* __restrict__ b_proj, const float* __restrict__ w_mix,
                  const float* __restrict__ b_mix, const float* __restrict__ decay_values,
                  const float* __restrict__ caches, const int* __restrict__ index_p,
                  const float* __restrict__ b_out)
{
    constexpr int BK = 32;
    constexpr int NS = 3;
    constexpr int NT = DIMN / BK;              // 128 k-slabs
    constexpr int STAGE_FLOATS = 2 * 128 * BK; // A(16KB) + B(16KB)
    constexpr int STAGE_BYTES  = STAGE_FLOATS * 4;

    extern __shared__ float smem[];
    const uint32_t smemBase = smem_u32(smem);

    const int tid  = threadIdx.x;
    const int wid  = tid >> 5;
    const int lane = tid & 31;
    const int warpM = wid & 1;    // 0..1
    const int warpN = wid >> 1;   // 0..3
    const int grp = lane >> 2;    // 0..7
    const int tig = lane & 3;     // 0..3

    const int row0 = blockIdx.y * 128;
    const int n0   = blockIdx.x * 128;
    const float* aBase = A + (size_t)row0 * DIMN;
    const float* bBase = B + (size_t)n0 * DIMN;

    // ---- async tile loader: identical to champion ----
    auto load = [&](int s, int kt) {
        const uint32_t sA = smemBase + s * STAGE_BYTES;
        const uint32_t sB = sA + 16384;
        #pragma unroll
        for (int i = 0; i < 4; i++) {
            const int g = tid + i * 256;       // 0..1023
            const int r = g >> 3, ch = g & 7;
            const uint32_t swoff = (uint32_t)(r * 128 + ((ch ^ (r & 7)) << 4));
            const float* srcA = aBase + (size_t)r * DIMN + kt + ch * 4;
            const float* srcB = bBase + (size_t)r * DIMN + kt + ch * 4;
            asm volatile("cp.async.cg.shared.global [%0], [%1], 16;"
                         :: "r"(sA + swoff), "l"(srcA));
            asm volatile("cp.async.cg.shared.global [%0], [%1], 16;"
                         :: "r"(sB + swoff), "l"(srcB));
        }
        asm volatile("cp.async.commit_group;");
    };

    // ---- per-thread ldmatrix row/swizzle offsets (stage-invariant) ----
    const int lane15 = lane & 15;
    const int lane7  = lane & 7;
    const int hiA = (lane >> 4) & 1;   // A: matrices 0,1 = ch0 ; 2,3 = ch1
    const int hiB = (lane >> 3) & 1;   // B: matrices 0,2 = ch0 ; 1,3 = ch1
    // A matrix row supplier: lane i -> block row (i&15), chunk ki*2+hiA
    const uint32_t aRowOff = (uint32_t)((warpM * 64 + lane15) * 128);
    // B matrix row supplier: lane i -> n-row warpN*32 + ((i>>4)&1)*8 + (i&7)
    const uint32_t bRowOff = (uint32_t)((warpN * 32 + ((lane >> 4) & 1) * 8 + lane7) * 128);
    uint32_t sxa[4], sxb[4];
    #pragma unroll
    for (int ki = 0; ki < 4; ki++) {
        sxa[ki] = (uint32_t)((((ki * 2 + hiA) ^ lane7) << 4));
        sxb[ki] = (uint32_t)((((ki * 2 + hiB) ^ lane7) << 4));
    }

    float acc[4][4][4];
    #pragma unroll
    for (int mi = 0; mi < 4; mi++)
        #pragma unroll
        for (int ni = 0; ni < 4; ni++)
            #pragma unroll
            for (int v = 0; v < 4; v++) acc[mi][ni][v] = 0.0f;

    load(0, 0);
    load(1, BK);

    for (int t = 0; t < NT; t++) {
        if (t < NT - 1) asm volatile("cp.async.wait_group 1;" ::: "memory");
        else            asm volatile("cp.async.wait_group 0;" ::: "memory");
        __syncthreads();

        if (t + 2 < NT) load((t + 2) % NS, (t + 2) * BK);

        const uint32_t sA = smemBase + (t % NS) * STAGE_BYTES;
        const uint32_t sB = sA + 16384;

        #pragma unroll
        for (int ki = 0; ki < 4; ki++) {
            // A fragments: 4 LDSM.x4 (regs j = a[mi][j], identical to champion)
            uint32_t a[4][4];
            {
                const uint32_t base = sA + aRowOff + sxa[ki];
                #pragma unroll
                for (int mi = 0; mi < 4; mi++)
                    ldsm4(a[mi], base + mi * 2048);
            }
            // B fragments: 2 LDSM.x4
            // regs: {b[0][0], b[0][1], b[1][0], b[1][1]} and ni+2 pair
            uint32_t b01[4], b23[4];
            {
                const uint32_t base = sB + bRowOff + sxb[ki];
                ldsm4(b01, base);
                ldsm4(b23, base + 2048);
            }
            const uint32_t* bfr[4] = { &b01[0], &b01[2], &b23[0], &b23[2] };
            #pragma unroll
            for (int mi = 0; mi < 4; mi++)
                #pragma unroll
                for (int ni = 0; ni < 4; ni++)
                    asm volatile(
                        "mma.sync.aligned.m16n8k8.row.col.f32.tf32.tf32.f32 "
                        "{%0,%1,%2,%3}, {%4,%5,%6,%7}, {%8,%9}, {%0,%1,%2,%3};"
                        : "+f"(acc[mi][ni][0]), "+f"(acc[mi][ni][1]),
                          "+f"(acc[mi][ni][2]), "+f"(acc[mi][ni][3])
                        : "r"(a[mi][0]), "r"(a[mi][1]), "r"(a[mi][2]), "r"(a[mi][3]),
                          "r"(bfr[ni][0]), "r"(bfr[ni][1]));
        }
    }

    // ------------------------------ epilogue (float2 stores) --------------
    if (MODE == 1) {
        const int h  = blockIdx.x >> 1;
        const int k0 = (blockIdx.x & 1) * 128;
        const int idx = *index_p;
        float dv = fminf(fmaxf(decay_values[h], 0.9f), 1.0f);
        const float decay = sqrtf(sqrtf(dv));
        const float w  = w_mix[(size_t)h * SEQL + idx];
        const float bb = b_mix[(size_t)h * SEQL + idx];
        const float coef = (h < NHEAD / 2) ? (w * decay) : decay;

        #pragma unroll
        for (int mi = 0; mi < 4; mi++) {
            #pragma unroll
            for (int half = 0; half < 2; half++) {
                const int r = row0 + warpM * 64 + mi * 16 + grp + half * 8;
                const float* cacheRow = caches + ((size_t)h * BATCH + r) * HIDN;
                float* Crow = C + (size_t)r * DIMN + n0;
                #pragma unroll
                for (int ni = 0; ni < 4; ni++) {
                    const int cc = warpN * 32 + ni * 8 + 2 * tig;   // even
                    const int k  = k0 + cc;
                    float2 v;
                    v.x = rna_tf32(w * (acc[mi][ni][half * 2 + 0] + b_proj[h * HIDN + k])
                                   + coef * cacheRow[k] + bb);
                    v.y = rna_tf32(w * (acc[mi][ni][half * 2 + 1] + b_proj[h * HIDN + k + 1])
                                   + coef * cacheRow[k + 1] + bb);
                    *reinterpret_cast<float2*>(Crow + cc) = v;
                }
            }
        }
    } else {
        #pragma unroll
        for (int mi = 0; mi < 4; mi++) {
            #pragma unroll
            for (int half = 0; half < 2; half++) {
                const int r = row0 + warpM * 64 + mi * 16 + grp + half * 8;
                float* Crow = C + (size_t)r * DIMN + n0;
                #pragma unroll
                for (int ni = 0; ni < 4; ni++) {
                    const int cc = warpN * 32 + ni * 8 + 2 * tig;
                    float2 v;
                    v.x = acc[mi][ni][half * 2 + 0] + b_out[n0 + cc];
                    v.y = acc[mi][ni][half * 2 + 1] + b_out[n0 + cc + 1];
                    *reinterpret_cast<float2*>(Crow + cc) = v;
                }
            }
        }
    }
}

// ---------------------------------------------------------------------------
extern "C" void kernel_launch(void* const* d_in, const int* in_sizes, int n_in,
                              void* d_out, int out_size)
{
    const float* x       = (const float*)d_in[0];
    const int*   index_p = (const int*)  d_in[1];
    const float* W_proj  = (const float*)d_in[2];
    const float* b_proj  = (const float*)d_in[3];
    const float* W_out   = (const float*)d_in[4];
    const float* b_out   = (const float*)d_in[5];
    const float* w_mix   = (const float*)d_in[6];
    const float* b_mix   = (const float*)d_in[7];
    const float* decay   = (const float*)d_in[8];
    const float* caches  = (const float*)d_in[9];
    float* out = (float*)d_out;

    float *hidden, *xr, *bt1, *bt2;
    cudaGetSymbolAddress((void**)&hidden, g_hidden);
    cudaGetSymbolAddress((void**)&xr,     g_xr);
    cudaGetSymbolAddress((void**)&bt1,    g_bt1);
    cudaGetSymbolAddress((void**)&bt2,    g_bt2);

    const int SMEM_DYN = 3 * 2 * 128 * 32 * 4;  // 96 KB
    cudaFuncSetAttribute(gemm_tf32mma<1>, cudaFuncAttributeMaxDynamicSharedMemorySize, SMEM_DYN);
    cudaFuncSetAttribute(gemm_tf32mma<2>, cudaFuncAttributeMaxDynamicSharedMemorySize, SMEM_DYN);

    {
        const int n4 = (BATCH * DIMN) / 4;
        round_tf32_kernel<<<(n4 + 255) / 256, 256>>>((const float4*)x, (float4*)xr, n4);
    }
    transpose_round_kernel<<<dim3(HIDN / 32, DIMN / 32, NHEAD), dim3(32, 8)>>>(
        W_proj, bt1, DIMN, HIDN);
    transpose_round_kernel<<<dim3(DIMN / 32, DIMN / 32, 1), dim3(32, 8)>>>(
        W_out, bt2, DIMN, DIMN);

    dim3 grid(DIMN / 128, BATCH / 128);   // 32 x 64
    gemm_tf32mma<1><<<grid, 256, SMEM_DYN>>>(xr, bt1, hidden,
                                             b_proj, w_mix, b_mix, decay, caches,
                                             index_p, b_out);
    gemm_tf32mma<2><<<grid, 256, SMEM_DYN>>>(hidden, bt2, out,
                                             b_proj, w_mix, b_mix, decay, caches,
                                             index_p, b_out);
}